// round 1
// baseline (speedup 1.0000x reference)
#include <cuda_runtime.h>

#define MROWS 16384
#define CDIM  1024
#define TSEQ  2048
#define BBAT  8
#define HHEAD 16

// ---------------- scratch (static __device__ allocations only) ----------------
__device__ float g_r  [(size_t)MROWS*CDIM];
__device__ float g_k  [(size_t)MROWS*CDIM];
__device__ float g_v  [(size_t)MROWS*CDIM];
__device__ float g_g  [(size_t)MROWS*CDIM];
__device__ float g_wkv[(size_t)MROWS*CDIM];
__device__ float g_xn [(size_t)MROWS*CDIM];
__device__ float2 g_stats[BBAT*HHEAD];
__device__ float g_state_scratch[BBAT*HHEAD*64*64];

enum { EPI_NONE=0, EPI_SIG=1, EPI_SILU=2, EPI_GOUT=3 };

__device__ __forceinline__ float sigf(float x){ return 1.0f/(1.0f+__expf(-x)); }

__device__ __forceinline__ float4 blend4(float4 a, float4 s, float4 m){
    float4 r;
    r.x = a.x*m.x + s.x*(1.0f-m.x);
    r.y = a.y*m.y + s.y*(1.0f-m.y);
    r.z = a.z*m.z + s.z*(1.0f-m.z);
    r.w = a.w*m.w + s.w*(1.0f-m.w);
    return r;
}

// ---------------- SGEMM: out[m][n] = act( sum_k A[m][k]*W[n][k] + bias[n] ) ----
// MIX=true : A[m][k] = x[m][k]*mix[k] + x[m-1][k]*(1-mix[k])   (x_shift fused)
// MIX=false: A = g_xn (group-normed wkv), epilogue GOUT multiplies by g_g.
template<int EPI, bool MIX>
__global__ __launch_bounds__(256, 2)
void sgemm_kernel(const float* __restrict__ xext,
                  const float* __restrict__ W,
                  const float* __restrict__ bias,
                  const float* __restrict__ mix,
                  float* __restrict__ out_ext,
                  int out_sel)
{
    __shared__ float As[8][132];
    __shared__ float Bs[8][132];

    const float* A = MIX ? xext : g_xn;
    float* out = (out_sel==0)?g_r:(out_sel==1)?g_k:(out_sel==2)?g_v:(out_sel==3)?g_g:out_ext;

    const int tid = threadIdx.x;
    const int bm = blockIdx.y, bn = blockIdx.x;
    const int lrow = tid >> 1;          // 0..127
    const int kq   = (tid & 1) * 4;     // 0 or 4
    const int gm   = bm*128 + lrow;
    const float* aptr = A + (size_t)gm*CDIM + kq;
    const float* wptr = W + (size_t)(bn*128 + lrow)*CDIM + kq;
    const bool hs = MIX && ((gm % TSEQ) != 0);

    float4 ra, rb;
    {
        float4 xa = *(const float4*)aptr;
        if (MIX){
            float4 mv = *(const float4*)(mix + kq);
            float4 xs = hs ? *(const float4*)(aptr - CDIM) : make_float4(0,0,0,0);
            ra = blend4(xa, xs, mv);
        } else ra = xa;
        rb = *(const float4*)wptr;
    }

    const int ty = tid >> 4, tx = tid & 15;
    float acc[8][8];
    #pragma unroll
    for (int i=0;i<8;i++)
        #pragma unroll
        for (int j=0;j<8;j++) acc[i][j]=0.f;

    for (int kt=0; kt<CDIM/8; kt++){
        As[kq+0][lrow]=ra.x; As[kq+1][lrow]=ra.y; As[kq+2][lrow]=ra.z; As[kq+3][lrow]=ra.w;
        Bs[kq+0][lrow]=rb.x; Bs[kq+1][lrow]=rb.y; Bs[kq+2][lrow]=rb.z; Bs[kq+3][lrow]=rb.w;
        __syncthreads();
        if (kt+1 < CDIM/8){
            const int ko = (kt+1)*8;
            float4 xa = *(const float4*)(aptr + ko);
            if (MIX){
                float4 mv = *(const float4*)(mix + ko + kq);
                float4 xs = hs ? *(const float4*)(aptr - CDIM + ko) : make_float4(0,0,0,0);
                ra = blend4(xa, xs, mv);
            } else ra = xa;
            rb = *(const float4*)(wptr + ko);
        }
        #pragma unroll
        for (int kk=0;kk<8;kk++){
            float4 a0 = *(const float4*)&As[kk][ty*4];
            float4 a1 = *(const float4*)&As[kk][ty*4+64];
            float4 b0 = *(const float4*)&Bs[kk][tx*4];
            float4 b1 = *(const float4*)&Bs[kk][tx*4+64];
            float a[8]={a0.x,a0.y,a0.z,a0.w,a1.x,a1.y,a1.z,a1.w};
            float b[8]={b0.x,b0.y,b0.z,b0.w,b1.x,b1.y,b1.z,b1.w};
            #pragma unroll
            for (int i=0;i<8;i++)
                #pragma unroll
                for (int j=0;j<8;j++)
                    acc[i][j] = fmaf(a[i], b[j], acc[i][j]);
        }
        __syncthreads();
    }

    // epilogue
    #pragma unroll
    for (int ih=0; ih<2; ih++){
        #pragma unroll
        for (int ii=0; ii<4; ii++){
            const int gr = bm*128 + ty*4 + ih*64 + ii;
            #pragma unroll
            for (int jh=0; jh<2; jh++){
                const int gc = bn*128 + tx*4 + jh*64;
                float4 bb4 = *(const float4*)(bias + gc);
                float v[4];
                #pragma unroll
                for (int jj=0;jj<4;jj++){
                    float t = acc[ih*4+ii][jh*4+jj] + ((const float*)&bb4)[jj];
                    if (EPI==EPI_SIG)       t = sigf(t);
                    else if (EPI==EPI_SILU) t = t*sigf(t);
                    v[jj]=t;
                }
                if (EPI==EPI_GOUT){
                    float4 gg = *(const float4*)(g_g + (size_t)gr*CDIM + gc);
                    v[0]*=gg.x; v[1]*=gg.y; v[2]*=gg.z; v[3]*=gg.w;
                }
                *(float4*)(out + (size_t)gr*CDIM + gc) = make_float4(v[0],v[1],v[2],v[3]);
            }
        }
    }
}

// ---------------- per-(token,head) L2 normalization of k and v -----------------
__global__ void l2norm_kernel()
{
    const int gwarp = (blockIdx.x*blockDim.x + threadIdx.x) >> 5;
    const int lane  = threadIdx.x & 31;
    float* arr = (blockIdx.y == 0) ? g_k : g_v;
    const size_t off = (size_t)gwarp*64;
    float v0 = arr[off+lane], v1 = arr[off+lane+32];
    float ss = v0*v0 + v1*v1;
    #pragma unroll
    for (int o=16;o;o>>=1) ss += __shfl_xor_sync(0xffffffffu, ss, o);
    const float n  = sqrtf(ss);
    const float sc = 1.0f/fmaxf(n, 1e-12f);
    arr[off+lane]    = v0*sc;
    arr[off+lane+32] = v1*sc;
}

// ---------------- sequential delta-rule scan: 1 CTA per (b,h) ------------------
// Thread i owns state row i (64 regs). Deferred scalar c: S_actual = c*S.
__global__ __launch_bounds__(64)
void scan_kernel(const float* __restrict__ decay, const float* __restrict__ eta,
                 float* __restrict__ state_out)
{
    const int bh = blockIdx.x;
    const int b = bh >> 4, h = bh & 15;
    const int i = threadIdx.x;
    const int lane = i & 31, wid = i >> 5;
    __shared__ float sk[64], sr[64];
    __shared__ float red[2];
    __shared__ double redd[2][2];

    float S[64];
    #pragma unroll
    for (int j=0;j<64;j++) S[j]=0.f;
    float c = 1.0f;
    const float dec = 1.0f/(1.0f+expf(-decay[h]));
    const float et  = 1.0f/(1.0f+expf(-eta[h]));
    const float maxn = 16.0f;   // sqrt(64)*2
    double wsum = 0.0, wsq = 0.0;

    const size_t base = (size_t)b*TSEQ*CDIM + (size_t)h*64;
    const float* kp = g_k   + base;
    const float* rp = g_r   + base;
    const float* vp = g_v   + base;
    float*       wp = g_wkv + base;

    float nk = kp[i], nr = rp[i], nv = vp[i];

    for (int t=0; t<TSEQ; t++){
        sk[i] = nk; sr[i] = nr;
        const float vi = nv;
        __syncthreads();
        if (t+1 < TSEQ){   // prefetch next step (latency hidden behind compute)
            nk = kp[CDIM+i]; nr = rp[CDIM+i]; nv = vp[CDIM+i];
        }
        const float4* sk4 = (const float4*)sk;
        // q = S_row . k
        float q0=0,q1=0,q2=0,q3=0;
        #pragma unroll
        for (int j=0;j<16;j++){
            float4 kv = sk4[j];
            q0 = fmaf(S[4*j+0], kv.x, q0);
            q1 = fmaf(S[4*j+1], kv.y, q1);
            q2 = fmaf(S[4*j+2], kv.z, q2);
            q3 = fmaf(S[4*j+3], kv.w, q3);
        }
        const float q = (q0+q1)+(q2+q3);
        const float err = c*q - vi;          // pred - v
        const float c1  = dec*c;             // scalar after decay
        const float coef = (et*err)/c1;      // rank-1 coefficient in stored units
        // S -= coef * k  (fused with squared-norm accumulation)
        float s0=0,s1=0,s2=0,s3=0;
        #pragma unroll
        for (int j=0;j<16;j++){
            float4 kv = sk4[j];
            float t0 = fmaf(-coef, kv.x, S[4*j+0]); S[4*j+0]=t0; s0 = fmaf(t0,t0,s0);
            float t1 = fmaf(-coef, kv.y, S[4*j+1]); S[4*j+1]=t1; s1 = fmaf(t1,t1,s1);
            float t2 = fmaf(-coef, kv.z, S[4*j+2]); S[4*j+2]=t2; s2 = fmaf(t2,t2,s2);
            float t3 = fmaf(-coef, kv.w, S[4*j+3]); S[4*j+3]=t3; s3 = fmaf(t3,t3,s3);
        }
        float ss = (s0+s1)+(s2+s3);
        #pragma unroll
        for (int o=16;o;o>>=1) ss += __shfl_xor_sync(0xffffffffu, ss, o);
        if (lane==0) red[wid]=ss;
        __syncthreads();
        const float tot = red[0]+red[1];
        const float nrm = c1*sqrtf(tot);     // actual Frobenius norm
        c = (nrm > maxn) ? c1*(maxn/nrm) : c1;
        // wkv = c * (S_row . r)
        const float4* sr4 = (const float4*)sr;
        float w0=0,w1=0,w2=0,w3=0;
        #pragma unroll
        for (int j=0;j<16;j++){
            float4 rv = sr4[j];
            w0 = fmaf(S[4*j+0], rv.x, w0);
            w1 = fmaf(S[4*j+1], rv.y, w1);
            w2 = fmaf(S[4*j+2], rv.z, w2);
            w3 = fmaf(S[4*j+3], rv.w, w3);
        }
        const float wv = c*((w0+w1)+(w2+w3));
        wp[i] = wv;
        wsum += (double)wv;
        wsq  += (double)wv*(double)wv;
        if ((t & 31)==31){                   // refold scalar to avoid underflow
            #pragma unroll
            for (int j=0;j<64;j++) S[j]*=c;
            c = 1.0f;
        }
        kp += CDIM; rp += CDIM; vp += CDIM; wp += CDIM;
        __syncthreads();
    }
    // group-norm stats over (T, D) for this (b,h)
    double a1=wsum, a2=wsq;
    #pragma unroll
    for (int o=16;o;o>>=1){
        a1 += __shfl_xor_sync(0xffffffffu, a1, o);
        a2 += __shfl_xor_sync(0xffffffffu, a2, o);
    }
    if (lane==0){ redd[wid][0]=a1; redd[wid][1]=a2; }
    __syncthreads();
    if (i==0){
        const double t1 = redd[0][0]+redd[1][0];
        const double t2 = redd[0][1]+redd[1][1];
        const double mean = t1 / (double)(TSEQ*64);
        const double var  = t2 / (double)(TSEQ*64) - mean*mean;
        g_stats[bh] = make_float2((float)mean, (float)(1.0/sqrt(var + 1e-5)));
    }
    float* so = state_out ? state_out : g_state_scratch;
    #pragma unroll
    for (int j=0;j<64;j++)
        so[(size_t)bh*4096 + (size_t)i*64 + j] = c*S[j];
}

// ---------------- group norm (per (b,h) stats, affine) -------------------------
__global__ void gnorm_kernel(const float* __restrict__ gnw, const float* __restrict__ gnb)
{
    const size_t idx = ((size_t)blockIdx.x*blockDim.x + threadIdx.x)*4;
    const int m  = (int)(idx / CDIM);
    const int cc = (int)(idx % CDIM);
    const int bh = (m >> 11)*HHEAD + (cc >> 6);   // m/2048 = batch
    const float2 st = g_stats[bh];
    float4 w  = *(const float4*)(g_wkv + idx);
    float4 gw = *(const float4*)(gnw + cc);
    float4 gb = *(const float4*)(gnb + cc);
    float4 o;
    o.x = (w.x - st.x)*st.y*gw.x + gb.x;
    o.y = (w.y - st.x)*st.y*gw.y + gb.y;
    o.z = (w.z - st.x)*st.y*gw.z + gb.z;
    o.w = (w.w - st.x)*st.y*gw.w + gb.w;
    *(float4*)(g_xn + idx) = o;
}

// ---------------- last_x = x[:, -1, :] -----------------------------------------
__global__ void lastx_kernel(const float* __restrict__ x, float* __restrict__ outp)
{
    const int i = blockIdx.x*blockDim.x + threadIdx.x;
    if (i >= BBAT*CDIM) return;
    const int b  = i >> 10;
    const int cc = i & (CDIM-1);
    outp[i] = x[((size_t)b*TSEQ + (TSEQ-1))*CDIM + cc];
}

// ---------------- launch ---------------------------------------------------------
extern "C" void kernel_launch(void* const* d_in, const int* in_sizes, int n_in,
                              void* d_out, int out_size)
{
    const float* x    = (const float*)d_in[0];
    const float* W_r  = (const float*)d_in[1];
    const float* b_r  = (const float*)d_in[2];
    const float* W_k  = (const float*)d_in[3];
    const float* b_k  = (const float*)d_in[4];
    const float* W_v  = (const float*)d_in[5];
    const float* b_v  = (const float*)d_in[6];
    const float* W_g  = (const float*)d_in[7];
    const float* b_g  = (const float*)d_in[8];
    const float* W_o  = (const float*)d_in[9];
    const float* b_o  = (const float*)d_in[10];
    const float* decay= (const float*)d_in[11];
    const float* eta  = (const float*)d_in[12];
    const float* mixr = (const float*)d_in[13];
    const float* mixk = (const float*)d_in[14];
    const float* mixv = (const float*)d_in[15];
    const float* mixg = (const float*)d_in[16];
    const float* gnw  = (const float*)d_in[17];
    const float* gnb  = (const float*)d_in[18];
    float* out = (float*)d_out;

    const int MAIN  = MROWS*CDIM;               // 16777216
    const int STATE = BBAT*HHEAD*64*64;         // 524288
    const int LASTX = BBAT*CDIM;                // 8192
    const bool full = out_size >= MAIN + STATE + LASTX;

    dim3 grid(8, 128);  // (N/128, M/128)
    sgemm_kernel<EPI_SIG,  true ><<<grid,256>>>(x, W_r, b_r, mixr, nullptr, 0);
    sgemm_kernel<EPI_NONE, true ><<<grid,256>>>(x, W_k, b_k, mixk, nullptr, 1);
    sgemm_kernel<EPI_NONE, true ><<<grid,256>>>(x, W_v, b_v, mixv, nullptr, 2);
    sgemm_kernel<EPI_SILU, true ><<<grid,256>>>(x, W_g, b_g, mixg, nullptr, 3);
    l2norm_kernel<<<dim3(32768,2),256>>>();
    scan_kernel<<<128,64>>>(decay, eta, full ? (out + MAIN) : nullptr);
    gnorm_kernel<<<16384,256>>>(gnw, gnb);
    sgemm_kernel<EPI_GOUT, false><<<grid,256>>>(nullptr, W_o, b_o, nullptr, out, 99);
    if (full) lastx_kernel<<<32,256>>>(x, out + MAIN + STATE);
}

// round 2
// speedup vs baseline: 1.3018x; 1.3018x over previous
#include <cuda_runtime.h>
#include <cstdint>

#define MROWS 16384
#define CDIM  1024
#define TSEQ  2048
#define BBAT  8
#define HHEAD 16

// ---------------- scratch (static __device__ allocations only) ----------------
__device__ float g_r  [(size_t)MROWS*CDIM];
__device__ float g_k  [(size_t)MROWS*CDIM];
__device__ float g_v  [(size_t)MROWS*CDIM];
__device__ float g_g  [(size_t)MROWS*CDIM];
__device__ float g_wkv[(size_t)MROWS*CDIM];
__device__ float2 g_stats[BBAT*HHEAD];
__device__ float g_state_scratch[BBAT*HHEAD*64*64];

enum { EPI_NONE=0, EPI_SIG=1, EPI_SILU=2, EPI_GOUT=3 };

__device__ __forceinline__ float sigf(float x){ return 1.0f/(1.0f+__expf(-x)); }

__device__ __forceinline__ void split_tf32(float a, uint32_t& hi, uint32_t& lo){
    uint32_t h;
    asm("cvt.rna.tf32.f32 %0, %1;" : "=r"(h) : "f"(a));
    hi = h;
    lo = __float_as_uint(a - __uint_as_float(h));
}

__device__ __forceinline__ void mma_tf32(float* c, const uint32_t* a, const uint32_t* b){
    asm volatile("mma.sync.aligned.m16n8k8.row.col.f32.tf32.tf32.f32 "
        "{%0,%1,%2,%3}, {%4,%5,%6,%7}, {%8,%9}, {%0,%1,%2,%3};"
        : "+f"(c[0]), "+f"(c[1]), "+f"(c[2]), "+f"(c[3])
        : "r"(a[0]), "r"(a[1]), "r"(a[2]), "r"(a[3]), "r"(b[0]), "r"(b[1]));
}

// =====================================================================
// tf32x3 GEMM: out[m][n] = act( sum_k A[m][k]*W[n][k] + bias[n] )
// AMODE 0: A = x*mix + x_shift*(1-mix)        (token-shift fused)
// AMODE 1: A = groupnorm(g_wkv) (stats from scan, affine gnw/gnb fused)
// Block 128x128, 4 warps (2x2 of 64x64 warp tiles), BK=16, double-buffered.
// =====================================================================
template<int EPI, int AMODE>
__global__ __launch_bounds__(128, 2)
void mma_gemm(const float* __restrict__ x,
              const float* __restrict__ W,
              const float* __restrict__ bias,
              const float* __restrict__ mix,
              const float* __restrict__ gnw,
              const float* __restrict__ gnb,
              float* __restrict__ out_ext,
              int out_sel)
{
    __shared__ float As[2][16][132];   // [k][m] transposed
    __shared__ float Bs[2][16][132];   // [k][n] transposed

    float* out = (out_sel==0)?g_r:(out_sel==1)?g_k:(out_sel==2)?g_v:(out_sel==3)?g_g:out_ext;

    const int tid  = threadIdx.x;
    const int lane = tid & 31;
    const int warp = tid >> 5;
    const int warpM = warp >> 1, warpN = warp & 1;
    const int bm = blockIdx.y, bn = blockIdx.x;

    // loader mapping: each thread loads 4 float4 of A and 4 of B per stage
    const int lm  = tid >> 2;         // 0..31 (row within 32-row group)
    const int lk4 = (tid & 3) * 4;    // 0,4,8,12 within 16-wide K stage

    float c[4][8][4];
    #pragma unroll
    for (int i=0;i<4;i++)
        #pragma unroll
        for (int j=0;j<8;j++)
            #pragma unroll
            for (int q=0;q<4;q++) c[i][j][q]=0.f;

    float4 pa[4], pb[4];

    // ---- loader lambdas ----
    auto load_stage = [&](int kt){
        const int koff = kt*16 + lk4;
        #pragma unroll
        for (int i=0;i<4;i++){
            const int gm = bm*128 + lm + 32*i;
            if (AMODE==0){
                float4 xa = *(const float4*)(x + (size_t)gm*CDIM + koff);
                float4 mv = *(const float4*)(mix + koff);
                float4 xs = make_float4(0,0,0,0);
                if ((gm & (TSEQ-1)) != 0)
                    xs = *(const float4*)(x + (size_t)(gm-1)*CDIM + koff);
                pa[i].x = xa.x*mv.x + xs.x*(1.0f-mv.x);
                pa[i].y = xa.y*mv.y + xs.y*(1.0f-mv.y);
                pa[i].z = xa.z*mv.z + xs.z*(1.0f-mv.z);
                pa[i].w = xa.w*mv.w + xs.w*(1.0f-mv.w);
            } else {
                float4 w  = *(const float4*)(g_wkv + (size_t)gm*CDIM + koff);
                const int bh = (gm >> 11)*HHEAD + (koff >> 6);
                const float2 st = g_stats[bh];
                float4 gw = *(const float4*)(gnw + koff);
                float4 gb = *(const float4*)(gnb + koff);
                pa[i].x = (w.x - st.x)*st.y*gw.x + gb.x;
                pa[i].y = (w.y - st.x)*st.y*gw.y + gb.y;
                pa[i].z = (w.z - st.x)*st.y*gw.z + gb.z;
                pa[i].w = (w.w - st.x)*st.y*gw.w + gb.w;
            }
            const int gn = bn*128 + lm + 32*i;
            pb[i] = *(const float4*)(W + (size_t)gn*CDIM + koff);
        }
    };
    auto store_stage = [&](int buf){
        #pragma unroll
        for (int i=0;i<4;i++){
            const int m = lm + 32*i;
            As[buf][lk4+0][m]=pa[i].x; As[buf][lk4+1][m]=pa[i].y;
            As[buf][lk4+2][m]=pa[i].z; As[buf][lk4+3][m]=pa[i].w;
            Bs[buf][lk4+0][m]=pb[i].x; Bs[buf][lk4+1][m]=pb[i].y;
            Bs[buf][lk4+2][m]=pb[i].z; Bs[buf][lk4+3][m]=pb[i].w;
        }
    };

    load_stage(0);

    const int g4 = lane >> 2;     // groupID
    const int t4 = lane & 3;      // tid in group

    for (int kt=0; kt<CDIM/16; kt++){
        const int buf = kt & 1;
        store_stage(buf);
        __syncthreads();
        if (kt+1 < CDIM/16) load_stage(kt+1);

        #pragma unroll
        for (int ks=0; ks<2; ks++){
            const int kc = ks*8 + t4;
            uint32_t ah[4][4], al[4][4];
            #pragma unroll
            for (int mt=0; mt<4; mt++){
                const int m = warpM*64 + mt*16 + g4;
                split_tf32(As[buf][kc  ][m  ], ah[mt][0], al[mt][0]);
                split_tf32(As[buf][kc  ][m+8], ah[mt][1], al[mt][1]);
                split_tf32(As[buf][kc+4][m  ], ah[mt][2], al[mt][2]);
                split_tf32(As[buf][kc+4][m+8], ah[mt][3], al[mt][3]);
            }
            uint32_t bh_[8][2], bl_[8][2];
            #pragma unroll
            for (int nt=0; nt<8; nt++){
                const int n = warpN*64 + nt*8 + g4;
                split_tf32(Bs[buf][kc  ][n], bh_[nt][0], bl_[nt][0]);
                split_tf32(Bs[buf][kc+4][n], bh_[nt][1], bl_[nt][1]);
            }
            #pragma unroll
            for (int mt=0; mt<4; mt++)
                #pragma unroll
                for (int nt=0; nt<8; nt++){
                    mma_tf32(c[mt][nt], ah[mt], bh_[nt]);
                    mma_tf32(c[mt][nt], ah[mt], bl_[nt]);
                    mma_tf32(c[mt][nt], al[mt], bh_[nt]);
                }
        }
        __syncthreads();
    }

    // ---- epilogue ----
    #pragma unroll
    for (int mt=0; mt<4; mt++){
        const int r0 = bm*128 + warpM*64 + mt*16 + g4;
        const int r1 = r0 + 8;
        #pragma unroll
        for (int nt=0; nt<8; nt++){
            const int col = bn*128 + warpN*64 + nt*8 + t4*2;
            const float2 bb = *(const float2*)(bias + col);
            float v0 = c[mt][nt][0] + bb.x;
            float v1 = c[mt][nt][1] + bb.y;
            float v2 = c[mt][nt][2] + bb.x;
            float v3 = c[mt][nt][3] + bb.y;
            if (EPI==EPI_SIG){ v0=sigf(v0); v1=sigf(v1); v2=sigf(v2); v3=sigf(v3); }
            else if (EPI==EPI_SILU){ v0*=sigf(v0); v1*=sigf(v1); v2*=sigf(v2); v3*=sigf(v3); }
            else if (EPI==EPI_GOUT){
                float2 g0 = *(const float2*)(g_g + (size_t)r0*CDIM + col);
                float2 g1 = *(const float2*)(g_g + (size_t)r1*CDIM + col);
                v0*=g0.x; v1*=g0.y; v2*=g1.x; v3*=g1.y;
            }
            *(float2*)(out + (size_t)r0*CDIM + col) = make_float2(v0,v1);
            *(float2*)(out + (size_t)r1*CDIM + col) = make_float2(v2,v3);
        }
    }
}

// ---------------- per-(token,head) L2 normalization of k and v -----------------
__global__ void l2norm_kernel()
{
    const int gwarp = (blockIdx.x*blockDim.x + threadIdx.x) >> 5;
    const int lane  = threadIdx.x & 31;
    float* arr = (blockIdx.y == 0) ? g_k : g_v;
    const size_t off = (size_t)gwarp*64;
    float v0 = arr[off+lane], v1 = arr[off+lane+32];
    float ss = v0*v0 + v1*v1;
    #pragma unroll
    for (int o=16;o;o>>=1) ss += __shfl_xor_sync(0xffffffffu, ss, o);
    const float n  = sqrtf(ss);
    const float sc = 1.0f/fmaxf(n, 1e-12f);
    arr[off+lane]    = v0*sc;
    arr[off+lane+32] = v1*sc;
}

// ---------------- sequential delta-rule scan: 1 CTA (128 thr) per (b,h) --------
// Thread t owns half a state row: row = t>>1, cols [32*(t&1), +32). Deferred
// scalar c: S_actual = c*S.  Norm reduction overlapped with unscaled S·r dot.
__global__ __launch_bounds__(128)
void scan_kernel(const float* __restrict__ decay, const float* __restrict__ eta,
                 float* __restrict__ state_out)
{
    const int bh = blockIdx.x;
    const int b = bh >> 4, h = bh & 15;
    const int t_ = threadIdx.x;
    const int row = t_ >> 1, half = t_ & 1;
    const int lane = t_ & 31, wid = t_ >> 5;
    const int koff = half*32;
    __shared__ __align__(16) float sk[64], sr[64], sv[64];
    __shared__ float red[4];
    __shared__ double redd[4][2];

    float S[32];
    #pragma unroll
    for (int j=0;j<32;j++) S[j]=0.f;
    float c = 1.0f;
    const float dec = 1.0f/(1.0f+expf(-decay[h]));
    const float et  = 1.0f/(1.0f+expf(-eta[h]));
    const float maxn = 16.0f;
    double wsum = 0.0, wsq = 0.0;

    const size_t base = (size_t)b*TSEQ*CDIM + (size_t)h*64;
    const float* kp = g_k + base;
    const float* rp = g_r + base;
    const float* vp = g_v + base;
    float*       op = g_wkv + base;

    float nk=0.f, nr=0.f, nv=0.f;
    if (t_ < 64){ nk = kp[t_]; nv = vp[t_]; } else { nr = rp[t_-64]; }

    for (int t=0; t<TSEQ; t++){
        if (t_ < 64){ sk[t_]=nk; sv[t_]=nv; } else { sr[t_-64]=nr; }
        __syncthreads();
        if (t+1 < TSEQ){
            if (t_ < 64){ nk = kp[CDIM+t_]; nv = vp[CDIM+t_]; }
            else        { nr = rp[CDIM+t_-64]; }
        }
        // q partial over this half-row
        const float4* k4 = (const float4*)(sk + koff);
        float q0=0,q1=0,q2=0,q3=0;
        #pragma unroll
        for (int j=0;j<8;j++){
            float4 kv = k4[j];
            q0 = fmaf(S[4*j+0], kv.x, q0);
            q1 = fmaf(S[4*j+1], kv.y, q1);
            q2 = fmaf(S[4*j+2], kv.z, q2);
            q3 = fmaf(S[4*j+3], kv.w, q3);
        }
        float qp = (q0+q1)+(q2+q3);
        qp += __shfl_xor_sync(0xffffffffu, qp, 1);   // pair combine (full row dot)
        const float vi = sv[row];
        const float err  = c*qp - vi;
        const float c1   = dec*c;
        const float coef = (et*err)/c1;
        // update half-row + squared-norm partials
        float s0=0,s1=0,s2=0,s3=0;
        #pragma unroll
        for (int j=0;j<8;j++){
            float4 kv = k4[j];
            float t0 = fmaf(-coef, kv.x, S[4*j+0]); S[4*j+0]=t0; s0 = fmaf(t0,t0,s0);
            float t1 = fmaf(-coef, kv.y, S[4*j+1]); S[4*j+1]=t1; s1 = fmaf(t1,t1,s1);
            float t2 = fmaf(-coef, kv.z, S[4*j+2]); S[4*j+2]=t2; s2 = fmaf(t2,t2,s2);
            float t3 = fmaf(-coef, kv.w, S[4*j+3]); S[4*j+3]=t3; s3 = fmaf(t3,t3,s3);
        }
        float ss = (s0+s1)+(s2+s3);
        // unscaled wkv dot (independent of the ss reduction -> overlaps shfl latency)
        const float4* r4 = (const float4*)(sr + koff);
        float w0=0,w1=0,w2=0,w3=0;
        #pragma unroll
        for (int j=0;j<8;j++){
            float4 rv = r4[j];
            w0 = fmaf(S[4*j+0], rv.x, w0);
            w1 = fmaf(S[4*j+1], rv.y, w1);
            w2 = fmaf(S[4*j+2], rv.z, w2);
            w3 = fmaf(S[4*j+3], rv.w, w3);
        }
        #pragma unroll
        for (int o=16;o;o>>=1) ss += __shfl_xor_sync(0xffffffffu, ss, o);
        if (lane==0) red[wid]=ss;
        float wpart = (w0+w1)+(w2+w3);
        wpart += __shfl_xor_sync(0xffffffffu, wpart, 1);
        __syncthreads();
        const float tot = red[0]+red[1]+red[2]+red[3];
        const float nrm = c1*sqrtf(tot);
        c = (nrm > maxn) ? c1*(maxn/nrm) : c1;
        const float wv = c*wpart;
        if (half==0) op[row] = wv;
        wsum += (double)wv;               // counted twice (both halves) -> /2 later
        wsq  += (double)wv*(double)wv;
        if ((t & 31)==31){
            #pragma unroll
            for (int j=0;j<32;j++) S[j]*=c;
            c = 1.0f;
        }
        kp += CDIM; rp += CDIM; vp += CDIM; op += CDIM;
        __syncthreads();
    }
    // group-norm stats over (T, D) for this (b,h); each wv counted twice
    double a1=wsum, a2=wsq;
    #pragma unroll
    for (int o=16;o;o>>=1){
        a1 += __shfl_xor_sync(0xffffffffu, a1, o);
        a2 += __shfl_xor_sync(0xffffffffu, a2, o);
    }
    if (lane==0){ redd[wid][0]=a1; redd[wid][1]=a2; }
    __syncthreads();
    if (t_==0){
        const double t1 = redd[0][0]+redd[1][0]+redd[2][0]+redd[3][0];
        const double t2 = redd[0][1]+redd[1][1]+redd[2][1]+redd[3][1];
        const double cnt = 2.0*(double)TSEQ*64.0;
        const double mean = t1 / cnt;
        const double var  = t2 / cnt - mean*mean;
        g_stats[bh] = make_float2((float)mean, (float)(1.0/sqrt(var + 1e-5)));
    }
    float* so = state_out ? state_out : g_state_scratch;
    #pragma unroll
    for (int j=0;j<32;j++)
        so[(size_t)bh*4096 + (size_t)row*64 + koff + j] = c*S[j];
}

// ---------------- last_x = x[:, -1, :] -----------------------------------------
__global__ void lastx_kernel(const float* __restrict__ x, float* __restrict__ outp)
{
    const int i = blockIdx.x*blockDim.x + threadIdx.x;
    if (i >= BBAT*CDIM) return;
    const int b  = i >> 10;
    const int cc = i & (CDIM-1);
    outp[i] = x[((size_t)b*TSEQ + (TSEQ-1))*CDIM + cc];
}

// ---------------- launch ---------------------------------------------------------
extern "C" void kernel_launch(void* const* d_in, const int* in_sizes, int n_in,
                              void* d_out, int out_size)
{
    const float* x    = (const float*)d_in[0];
    const float* W_r  = (const float*)d_in[1];
    const float* b_r  = (const float*)d_in[2];
    const float* W_k  = (const float*)d_in[3];
    const float* b_k  = (const float*)d_in[4];
    const float* W_v  = (const float*)d_in[5];
    const float* b_v  = (const float*)d_in[6];
    const float* W_g  = (const float*)d_in[7];
    const float* b_g  = (const float*)d_in[8];
    const float* W_o  = (const float*)d_in[9];
    const float* b_o  = (const float*)d_in[10];
    const float* decay= (const float*)d_in[11];
    const float* eta  = (const float*)d_in[12];
    const float* mixr = (const float*)d_in[13];
    const float* mixk = (const float*)d_in[14];
    const float* mixv = (const float*)d_in[15];
    const float* mixg = (const float*)d_in[16];
    const float* gnw  = (const float*)d_in[17];
    const float* gnb  = (const float*)d_in[18];
    float* out = (float*)d_out;

    const int MAIN  = MROWS*CDIM;
    const int STATE = BBAT*HHEAD*64*64;
    const int LASTX = BBAT*CDIM;
    const bool full = out_size >= MAIN + STATE + LASTX;

    dim3 grid(8, 128);
    mma_gemm<EPI_SIG,  0><<<grid,128>>>(x, W_r, b_r, mixr, nullptr, nullptr, nullptr, 0);
    mma_gemm<EPI_NONE, 0><<<grid,128>>>(x, W_k, b_k, mixk, nullptr, nullptr, nullptr, 1);
    mma_gemm<EPI_NONE, 0><<<grid,128>>>(x, W_v, b_v, mixv, nullptr, nullptr, nullptr, 2);
    mma_gemm<EPI_SILU, 0><<<grid,128>>>(x, W_g, b_g, mixg, nullptr, nullptr, nullptr, 3);
    l2norm_kernel<<<dim3(32768,2),256>>>();
    scan_kernel<<<128,128>>>(decay, eta, full ? (out + MAIN) : nullptr);
    mma_gemm<EPI_GOUT, 1><<<grid,128>>>(nullptr, W_o, b_o, nullptr, gnw, gnb, out, 99);
    if (full) lastx_kernel<<<32,256>>>(x, out + MAIN + STATE);
}